// round 2
// baseline (speedup 1.0000x reference)
#include <cuda_runtime.h>

#define TT 512
#define BB 256
#define II 64
#define NN 512
#define NB (BB*NN)

// Static device scratch (allocation-free rule: __device__ globals only)
__device__ __align__(256) float g_Wc0[576 * NN];    // [Whh0(diag0) | Win]
__device__ __align__(256) float g_Wc1[1088 * NN];   // [Whh1(diag0) | Whi0 | Win]
__device__ __align__(256) float g_Wc2[1088 * NN];   // [Whh2(diag0) | Whi1 | Win]
__device__ __align__(256) float g_bc[3 * NN];       // folded biases
__device__ __align__(256) float g_S[2][3][NB];      // ping-pong hidden states

// ---------------------------------------------------------------------------
// Prep: concatenated weights, folded biases, init both state buffers.
// ---------------------------------------------------------------------------
__global__ void prep_kernel(const float* __restrict__ h0, const float* __restrict__ Win,
                            const float* __restrict__ b_in, const float* __restrict__ Whh,
                            const float* __restrict__ b_hh, const float* __restrict__ Whi,
                            const float* __restrict__ b_hi) {
    int tid = blockIdx.x * blockDim.x + threadIdx.x;
    int stride = gridDim.x * blockDim.x;

    for (int i = tid; i < 576 * NN; i += stride) {
        int k = i >> 9, n = i & 511;
        float v;
        if (k < 512) v = (k == n) ? 0.f : Whh[(0 * 512 + k) * 512 + n];
        else         v = Win[(k - 512) * 512 + n];
        g_Wc0[i] = v;
    }
    for (int i = tid; i < 1088 * NN; i += stride) {
        int k = i >> 9, n = i & 511;
        float v;
        if (k < 512)       v = (k == n) ? 0.f : Whh[(1 * 512 + k) * 512 + n];
        else if (k < 1024) v = Whi[(0 * 512 + (k - 512)) * 512 + n];
        else               v = Win[(k - 1024) * 512 + n];
        g_Wc1[i] = v;
    }
    for (int i = tid; i < 1088 * NN; i += stride) {
        int k = i >> 9, n = i & 511;
        float v;
        if (k < 512)       v = (k == n) ? 0.f : Whh[(2 * 512 + k) * 512 + n];
        else if (k < 1024) v = Whi[(1 * 512 + (k - 512)) * 512 + n];
        else               v = Win[(k - 1024) * 512 + n];
        g_Wc2[i] = v;
    }
    for (int i = tid; i < 3 * NN; i += stride) {
        int l = i >> 9, n = i & 511;
        float v = b_hh[i] + b_in[n];
        if (l > 0) v += b_hi[(l - 1) * 512 + n];
        g_bc[i] = v;
    }
    for (int i = tid; i < 3 * NB; i += stride) {
        float v = h0[i];
        (&g_S[0][0][0])[i] = v;
        (&g_S[1][0][0])[i] = v;
    }
}

// ---------------------------------------------------------------------------
// f32x2 helpers (packed FFMA2 — only path to 128 FMA/cyc/SM on sm_103a)
// ---------------------------------------------------------------------------
__device__ __forceinline__ unsigned long long bcast2(float x) {
    unsigned long long r;
    asm("mov.b64 %0,{%1,%1};" : "=l"(r) : "f"(x));
    return r;
}
__device__ __forceinline__ void fma2(unsigned long long& c, unsigned long long a,
                                     unsigned long long b) {
    asm("fma.rn.f32x2 %0,%1,%2,%0;" : "+l"(c) : "l"(a), "l"(b));
}
__device__ __forceinline__ float2 upk(unsigned long long v) {
    float2 f;
    asm("mov.b64 {%0,%1},%2;" : "=f"(f.x), "=f"(f.y) : "l"(v));
    return f;
}
__device__ __forceinline__ void cpa16(float* s, const float* g) {
    unsigned ss = (unsigned)__cvta_generic_to_shared(s);
    asm volatile("cp.async.cg.shared.global [%0],[%1],16;\n" ::"r"(ss), "l"(g));
}

// ---------------------------------------------------------------------------
// One output tile: rows = MR*16 (MR in {1,2}), cols = 64, K = nck*32.
// A segmented: [h_l | n_{l-1} | data_t] matching the concatenated weights.
// ---------------------------------------------------------------------------
template <int MR>
__device__ void run_tile(const float* __restrict__ data, int l, int t, int row0, int col0,
                         const float* __restrict__ Wc, int nck, int prev, int cur,
                         float (*As)[32 * 36], float (*Bs)[32 * 64]) {
    const int tid = threadIdx.x;
    const int tx = tid & 7;     // 8 col-groups
    const int ty = tid >> 3;    // 16 row-groups
    const int R = MR * 16;
    const int dbase = l ? 1024 : 512;

    unsigned long long acc[MR][4];
#pragma unroll
    for (int m = 0; m < MR; m++)
#pragma unroll
        for (int j = 0; j < 4; j++) acc[m][j] = 0ull;

    auto load_chunk = [&](int ci, int buf) {
        int k0 = ci * 32;
        const float* src;
        int strideA;
        if (k0 < 512)                { src = &g_S[prev][l][k0];           strideA = NN; }
        else if (l > 0 && k0 < 1024) { src = &g_S[prev][l - 1][k0 - 512]; strideA = NN; }
        else { src = data + (size_t)t * (BB * II) + (k0 - dbase);         strideA = II; }
        src += (size_t)row0 * strideA;
        for (int idx = tid; idx < R * 8; idx += 128) {
            int r = idx >> 3, q = idx & 7;
            cpa16(&As[buf][r * 36 + q * 4], src + (size_t)r * strideA + q * 4);
        }
        const float* wsrc = Wc + (size_t)k0 * NN + col0;
        for (int idx = tid; idx < 512; idx += 128) {
            int r = idx >> 4, q = idx & 15;
            cpa16(&Bs[buf][r * 64 + q * 4], wsrc + (size_t)r * NN + q * 4);
        }
        asm volatile("cp.async.commit_group;\n");
    };

    load_chunk(0, 0);
    for (int ci = 0; ci < nck; ci++) {
        int buf = ci & 1;
        if (ci + 1 < nck) {
            load_chunk(ci + 1, buf ^ 1);
            asm volatile("cp.async.wait_group 1;\n");
        } else {
            asm volatile("cp.async.wait_group 0;\n");
        }
        __syncthreads();
        const float* A = As[buf];
        const float* Bp = Bs[buf];
#pragma unroll 8
        for (int k = 0; k < 32; k++) {
            // cols: j*16 + tx*2 (+{0,1}) -> conflict-free LDS.64 across tx
            unsigned long long B0 = *(const unsigned long long*)&Bp[k * 64 + 0  + tx * 2];
            unsigned long long B1 = *(const unsigned long long*)&Bp[k * 64 + 16 + tx * 2];
            unsigned long long B2 = *(const unsigned long long*)&Bp[k * 64 + 32 + tx * 2];
            unsigned long long B3 = *(const unsigned long long*)&Bp[k * 64 + 48 + tx * 2];
#pragma unroll
            for (int m = 0; m < MR; m++) {
                unsigned long long ap = bcast2(A[(ty * MR + m) * 36 + k]);
                fma2(acc[m][0], ap, B0);
                fma2(acc[m][1], ap, B1);
                fma2(acc[m][2], ap, B2);
                fma2(acc[m][3], ap, B3);
            }
        }
        __syncthreads();
    }

    // finalize: n = lrelu(0.5*h + 0.5*(dot + bias)), slope 0.01
    float* dst = g_S[cur][l];
    const float* hold = g_S[prev][l];
    const float* bias = &g_bc[l * NN];
#pragma unroll
    for (int m = 0; m < MR; m++) {
        int gr = row0 + ty * MR + m;
#pragma unroll
        for (int j = 0; j < 4; j++) {
            float2 v = upk(acc[m][j]);
            int gc = col0 + j * 16 + tx * 2;
            float p0 = 0.5f * hold[gr * NN + gc]     + 0.5f * (v.x + bias[gc]);
            float p1 = 0.5f * hold[gr * NN + gc + 1] + 0.5f * (v.y + bias[gc + 1]);
            dst[gr * NN + gc]     = (p0 > 0.f) ? p0 : 0.01f * p0;
            dst[gr * NN + gc + 1] = (p1 > 0.f) ? p1 : 0.01f * p1;
        }
    }
}

// ---------------------------------------------------------------------------
// One wavefront tick: layer0@t=kk, layer1@t=kk-1, layer2@t=kk-2.
// 256 blocks, heavy/light jobs interleaved by parity for SM balance.
// ---------------------------------------------------------------------------
__global__ void __launch_bounds__(128) tick_kernel(const float* __restrict__ data, int kk) {
    __shared__ float As[2][32 * 36];
    __shared__ float Bs[2][32 * 64];
    const int cur = kk & 1;
    const int prev = cur ^ 1;
    const int b = blockIdx.x;

    if ((b & 1) == 0) {
        // heavy: 128 tiles of [32x64], K=1088 (layers 1 & 2)
        int j = b >> 1;                 // 0..127
        int l = 1 + (j >> 6);           // 1 or 2
        int jj = j & 63;
        int t = kk - l;
        if (t >= 0 && t < TT)
            run_tile<2>(data, l, t, (jj >> 3) * 32, (jj & 7) * 64,
                        (l == 1) ? g_Wc1 : g_Wc2, 34, prev, cur, As, Bs);
    } else {
        // light: 128 tiles of [16x64], K=576 (layer 0)
        int j = b >> 1;                 // 0..127
        if (kk < TT)
            run_tile<1>(data, 0, kk, (j >> 3) * 16, (j & 7) * 64,
                        g_Wc0, 18, prev, cur, As, Bs);
    }
}

// ---------------------------------------------------------------------------
// Readout: out[b][c] = n2_final[b] . Wfc[:,c] + b_fc[c]; one warp per output.
// n2(511) computed at tick 513 -> buffer 513&1 = 1.
// ---------------------------------------------------------------------------
__global__ void final_kernel(const float* __restrict__ Wfc, const float* __restrict__ bfc,
                             float* __restrict__ out) {
    int gw = (blockIdx.x * blockDim.x + threadIdx.x) >> 5;
    int lane = threadIdx.x & 31;
    if (gw >= BB * 10) return;
    int b = gw / 10, c = gw % 10;
    const float* h = &g_S[1][2][b * NN];
    float s = 0.f;
    for (int k = lane; k < NN; k += 32) s += h[k] * Wfc[k * 10 + c];
#pragma unroll
    for (int o = 16; o; o >>= 1) s += __shfl_down_sync(0xffffffffu, s, o);
    if (lane == 0) out[b * 10 + c] = s + bfc[c];
}

// ---------------------------------------------------------------------------
extern "C" void kernel_launch(void* const* d_in, const int* in_sizes, int n_in,
                              void* d_out, int out_size) {
    const float* data = (const float*)d_in[0];
    const float* h0   = (const float*)d_in[1];
    const float* Win  = (const float*)d_in[2];
    const float* b_in = (const float*)d_in[3];
    const float* Whh  = (const float*)d_in[4];
    const float* b_hh = (const float*)d_in[5];
    const float* Whi  = (const float*)d_in[6];
    const float* b_hi = (const float*)d_in[7];
    const float* Wfc  = (const float*)d_in[8];
    const float* b_fc = (const float*)d_in[9];
    float* out = (float*)d_out;

    prep_kernel<<<1024, 256>>>(h0, Win, b_in, Whh, b_hh, Whi, b_hi);
    for (int kk = 0; kk < TT + 2; kk++)
        tick_kernel<<<256, 128>>>(data, kk);
    final_kernel<<<320, 256>>>(Wfc, b_fc, out);
}

// round 3
// speedup vs baseline: 1.0002x; 1.0002x over previous
#include <cuda_runtime.h>

#define TT 512
#define BB 256
#define II 64
#define NN 512
#define NB (BB*NN)

// Static device scratch (allocation-free rule: __device__ globals only)
__device__ __align__(256) float g_Wc0[576 * NN];    // [Whh0(diag0) | Win]
__device__ __align__(256) float g_Wc1[1088 * NN];   // [Whh1(diag0) | Whi0 | Win]
__device__ __align__(256) float g_Wc2[1088 * NN];   // [Whh2(diag0) | Whi1 | Win]
__device__ __align__(256) float g_bc[3 * NN];       // folded biases
__device__ __align__(256) float g_S[2][3][NB];      // ping-pong hidden states

// ---------------------------------------------------------------------------
// Prep: concatenated weights, folded biases, init both state buffers.
// ---------------------------------------------------------------------------
__global__ void prep_kernel(const float* __restrict__ h0, const float* __restrict__ Win,
                            const float* __restrict__ b_in, const float* __restrict__ Whh,
                            const float* __restrict__ b_hh, const float* __restrict__ Whi,
                            const float* __restrict__ b_hi) {
    int tid = blockIdx.x * blockDim.x + threadIdx.x;
    int stride = gridDim.x * blockDim.x;

    for (int i = tid; i < 576 * NN; i += stride) {
        int k = i >> 9, n = i & 511;
        float v;
        if (k < 512) v = (k == n) ? 0.f : Whh[(0 * 512 + k) * 512 + n];
        else         v = Win[(k - 512) * 512 + n];
        g_Wc0[i] = v;
    }
    for (int i = tid; i < 1088 * NN; i += stride) {
        int k = i >> 9, n = i & 511;
        float v;
        if (k < 512)       v = (k == n) ? 0.f : Whh[(1 * 512 + k) * 512 + n];
        else if (k < 1024) v = Whi[(0 * 512 + (k - 512)) * 512 + n];
        else               v = Win[(k - 1024) * 512 + n];
        g_Wc1[i] = v;
    }
    for (int i = tid; i < 1088 * NN; i += stride) {
        int k = i >> 9, n = i & 511;
        float v;
        if (k < 512)       v = (k == n) ? 0.f : Whh[(2 * 512 + k) * 512 + n];
        else if (k < 1024) v = Whi[(1 * 512 + (k - 512)) * 512 + n];
        else               v = Win[(k - 1024) * 512 + n];
        g_Wc2[i] = v;
    }
    for (int i = tid; i < 3 * NN; i += stride) {
        int l = i >> 9, n = i & 511;
        float v = b_hh[i] + b_in[n];
        if (l > 0) v += b_hi[(l - 1) * 512 + n];
        g_bc[i] = v;
    }
    for (int i = tid; i < 3 * NB; i += stride) {
        float v = h0[i];
        (&g_S[0][0][0])[i] = v;
        (&g_S[1][0][0])[i] = v;
    }
}

// ---------------------------------------------------------------------------
// f32x2 helpers (packed FFMA2 — only path to 128 FMA/cyc/SM on sm_103a)
// ---------------------------------------------------------------------------
__device__ __forceinline__ unsigned long long bcast2(float x) {
    unsigned long long r;
    asm("mov.b64 %0,{%1,%1};" : "=l"(r) : "f"(x));
    return r;
}
__device__ __forceinline__ void fma2(unsigned long long& c, unsigned long long a,
                                     unsigned long long b) {
    asm("fma.rn.f32x2 %0,%1,%2,%0;" : "+l"(c) : "l"(a), "l"(b));
}
__device__ __forceinline__ float2 upk(unsigned long long v) {
    float2 f;
    asm("mov.b64 {%0,%1},%2;" : "=f"(f.x), "=f"(f.y) : "l"(v));
    return f;
}
__device__ __forceinline__ void cpa16(float* s, const float* g) {
    unsigned ss = (unsigned)__cvta_generic_to_shared(s);
    asm volatile("cp.async.cg.shared.global [%0],[%1],16;\n" ::"r"(ss), "l"(g));
}

// ---------------------------------------------------------------------------
// One output tile: rows = MR*16 (MR in {1,2}), cols = 64, K = nck*32.
// A segmented: [h_l | n_{l-1} | data_t] matching the concatenated weights.
// ---------------------------------------------------------------------------
template <int MR>
__device__ void run_tile(const float* __restrict__ data, int l, int t, int row0, int col0,
                         const float* __restrict__ Wc, int nck, int prev, int cur,
                         float (*As)[32 * 36], float (*Bs)[32 * 64]) {
    const int tid = threadIdx.x;
    const int tx = tid & 7;     // 8 col-groups
    const int ty = tid >> 3;    // 16 row-groups
    const int R = MR * 16;
    const int dbase = l ? 1024 : 512;

    unsigned long long acc[MR][4];
#pragma unroll
    for (int m = 0; m < MR; m++)
#pragma unroll
        for (int j = 0; j < 4; j++) acc[m][j] = 0ull;

    auto load_chunk = [&](int ci, int buf) {
        int k0 = ci * 32;
        const float* src;
        int strideA;
        if (k0 < 512)                { src = &g_S[prev][l][k0];           strideA = NN; }
        else if (l > 0 && k0 < 1024) { src = &g_S[prev][l - 1][k0 - 512]; strideA = NN; }
        else { src = data + (size_t)t * (BB * II) + (k0 - dbase);         strideA = II; }
        src += (size_t)row0 * strideA;
        for (int idx = tid; idx < R * 8; idx += 128) {
            int r = idx >> 3, q = idx & 7;
            cpa16(&As[buf][r * 36 + q * 4], src + (size_t)r * strideA + q * 4);
        }
        const float* wsrc = Wc + (size_t)k0 * NN + col0;
        for (int idx = tid; idx < 512; idx += 128) {
            int r = idx >> 4, q = idx & 15;
            cpa16(&Bs[buf][r * 64 + q * 4], wsrc + (size_t)r * NN + q * 4);
        }
        asm volatile("cp.async.commit_group;\n");
    };

    load_chunk(0, 0);
    for (int ci = 0; ci < nck; ci++) {
        int buf = ci & 1;
        if (ci + 1 < nck) {
            load_chunk(ci + 1, buf ^ 1);
            asm volatile("cp.async.wait_group 1;\n");
        } else {
            asm volatile("cp.async.wait_group 0;\n");
        }
        __syncthreads();
        const float* A = As[buf];
        const float* Bp = Bs[buf];
#pragma unroll 8
        for (int k = 0; k < 32; k++) {
            // cols: j*16 + tx*2 (+{0,1}) -> conflict-free LDS.64 across tx
            unsigned long long B0 = *(const unsigned long long*)&Bp[k * 64 + 0  + tx * 2];
            unsigned long long B1 = *(const unsigned long long*)&Bp[k * 64 + 16 + tx * 2];
            unsigned long long B2 = *(const unsigned long long*)&Bp[k * 64 + 32 + tx * 2];
            unsigned long long B3 = *(const unsigned long long*)&Bp[k * 64 + 48 + tx * 2];
#pragma unroll
            for (int m = 0; m < MR; m++) {
                unsigned long long ap = bcast2(A[(ty * MR + m) * 36 + k]);
                fma2(acc[m][0], ap, B0);
                fma2(acc[m][1], ap, B1);
                fma2(acc[m][2], ap, B2);
                fma2(acc[m][3], ap, B3);
            }
        }
        __syncthreads();
    }

    // finalize: n = lrelu(0.5*h + 0.5*(dot + bias)), slope 0.01
    float* dst = g_S[cur][l];
    const float* hold = g_S[prev][l];
    const float* bias = &g_bc[l * NN];
#pragma unroll
    for (int m = 0; m < MR; m++) {
        int gr = row0 + ty * MR + m;
#pragma unroll
        for (int j = 0; j < 4; j++) {
            float2 v = upk(acc[m][j]);
            int gc = col0 + j * 16 + tx * 2;
            float p0 = 0.5f * hold[gr * NN + gc]     + 0.5f * (v.x + bias[gc]);
            float p1 = 0.5f * hold[gr * NN + gc + 1] + 0.5f * (v.y + bias[gc + 1]);
            dst[gr * NN + gc]     = (p0 > 0.f) ? p0 : 0.01f * p0;
            dst[gr * NN + gc + 1] = (p1 > 0.f) ? p1 : 0.01f * p1;
        }
    }
}

// ---------------------------------------------------------------------------
// One wavefront tick: layer0@t=kk, layer1@t=kk-1, layer2@t=kk-2.
// 256 blocks, heavy/light jobs interleaved by parity for SM balance.
// ---------------------------------------------------------------------------
__global__ void __launch_bounds__(128) tick_kernel(const float* __restrict__ data, int kk) {
    __shared__ float As[2][32 * 36];
    __shared__ float Bs[2][32 * 64];
    const int cur = kk & 1;
    const int prev = cur ^ 1;
    const int b = blockIdx.x;

    if ((b & 1) == 0) {
        // heavy: 128 tiles of [32x64], K=1088 (layers 1 & 2)
        int j = b >> 1;                 // 0..127
        int l = 1 + (j >> 6);           // 1 or 2
        int jj = j & 63;
        int t = kk - l;
        if (t >= 0 && t < TT)
            run_tile<2>(data, l, t, (jj >> 3) * 32, (jj & 7) * 64,
                        (l == 1) ? g_Wc1 : g_Wc2, 34, prev, cur, As, Bs);
    } else {
        // light: 128 tiles of [16x64], K=576 (layer 0)
        int j = b >> 1;                 // 0..127
        if (kk < TT)
            run_tile<1>(data, 0, kk, (j >> 3) * 16, (j & 7) * 64,
                        g_Wc0, 18, prev, cur, As, Bs);
    }
}

// ---------------------------------------------------------------------------
// Readout: out[b][c] = n2_final[b] . Wfc[:,c] + b_fc[c]; one warp per output.
// n2(511) computed at tick 513 -> buffer 513&1 = 1.
// ---------------------------------------------------------------------------
__global__ void final_kernel(const float* __restrict__ Wfc, const float* __restrict__ bfc,
                             float* __restrict__ out) {
    int gw = (blockIdx.x * blockDim.x + threadIdx.x) >> 5;
    int lane = threadIdx.x & 31;
    if (gw >= BB * 10) return;
    int b = gw / 10, c = gw % 10;
    const float* h = &g_S[1][2][b * NN];
    float s = 0.f;
    for (int k = lane; k < NN; k += 32) s += h[k] * Wfc[k * 10 + c];
#pragma unroll
    for (int o = 16; o; o >>= 1) s += __shfl_down_sync(0xffffffffu, s, o);
    if (lane == 0) out[b * 10 + c] = s + bfc[c];
}

// ---------------------------------------------------------------------------
extern "C" void kernel_launch(void* const* d_in, const int* in_sizes, int n_in,
                              void* d_out, int out_size) {
    const float* data = (const float*)d_in[0];
    const float* h0   = (const float*)d_in[1];
    const float* Win  = (const float*)d_in[2];
    const float* b_in = (const float*)d_in[3];
    const float* Whh  = (const float*)d_in[4];
    const float* b_hh = (const float*)d_in[5];
    const float* Whi  = (const float*)d_in[6];
    const float* b_hi = (const float*)d_in[7];
    const float* Wfc  = (const float*)d_in[8];
    const float* b_fc = (const float*)d_in[9];
    float* out = (float*)d_out;

    prep_kernel<<<1024, 256>>>(h0, Win, b_in, Whh, b_hh, Whi, b_hi);
    for (int kk = 0; kk < TT + 2; kk++)
        tick_kernel<<<256, 128>>>(data, kk);
    final_kernel<<<320, 256>>>(Wfc, b_fc, out);
}

// round 5
// speedup vs baseline: 1.5741x; 1.5738x over previous
#include <cuda_runtime.h>

#define TT 512
#define BB 256
#define II 64
#define NN 512
#define NB (BB*NN)
#define NBLK 256

__device__ __align__(256) float g_Wc0[576 * NN];
__device__ __align__(256) float g_Wc1[1088 * NN];
__device__ __align__(256) float g_Wc2[1088 * NN];
__device__ __align__(256) float g_bc[3 * NN];
__device__ __align__(256) float g_S[2][3][NB];
__device__ __align__(256) float g_P[256 * 4096];
__device__ unsigned g_bar_cnt;   // zero-init at load; returns to 0 every barrier
__device__ unsigned g_bar_gen;

__device__ __forceinline__ unsigned long long bcast2(float x) {
    unsigned long long r;
    asm("mov.b64 %0,{%1,%1};" : "=l"(r) : "f"(x));
    return r;
}
__device__ __forceinline__ void fma2(unsigned long long& c, unsigned long long a,
                                     unsigned long long b) {
    asm("fma.rn.f32x2 %0,%1,%2,%0;" : "+l"(c) : "l"(a), "l"(b));
}
__device__ __forceinline__ float2 upk(unsigned long long v) {
    float2 f;
    asm("mov.b64 {%0,%1},%2;" : "=f"(f.x), "=f"(f.y) : "l"(v));
    return f;
}
__device__ __forceinline__ void cpa16(float* s, const float* g) {
    unsigned ss = (unsigned)__cvta_generic_to_shared(s);
    asm volatile("cp.async.cg.shared.global [%0],[%1],16;\n" ::"r"(ss), "l"(g));
}

// Grid barrier: all 256 blocks co-resident (verified occupancy), gen-poll at L2.
__device__ __forceinline__ void gridbar(unsigned& gen) {
    __threadfence();
    __syncthreads();
    if (threadIdx.x == 0) {
        unsigned g = gen;
        if (atomicAdd(&g_bar_cnt, 1u) == NBLK - 1u) {
            atomicExch(&g_bar_cnt, 0u);
            __threadfence();
            atomicExch(&g_bar_gen, g + 1u);
        } else {
            while (atomicAdd(&g_bar_gen, 0u) == g) __nanosleep(32);
        }
    }
    gen++;
    __syncthreads();
}

__global__ void __launch_bounds__(128) persist_kernel(
    const float* __restrict__ data, const float* __restrict__ h0,
    const float* __restrict__ Win, const float* __restrict__ b_in,
    const float* __restrict__ Whh, const float* __restrict__ b_hh,
    const float* __restrict__ Whi, const float* __restrict__ b_hi,
    const float* __restrict__ Wfc, const float* __restrict__ bfc,
    float* __restrict__ out) {
    __shared__ float As[2][64 * 36];
    __shared__ float Bs[2][32 * 64];

    const int tid = threadIdx.x;
    const int jid = blockIdx.x;
    unsigned gen = (tid == 0) ? atomicAdd(&g_bar_gen, 0u) : 0u;

    // ---- prep: concat weights, folded biases, init both state buffers ----
    {
        int gt = jid * 128 + tid;
        const int gs = NBLK * 128;
        for (int i = gt; i < 576 * NN; i += gs) {
            int k = i >> 9, n = i & 511;
            g_Wc0[i] = (k < 512) ? ((k == n) ? 0.f : Whh[k * 512 + n])
                                 : Win[(k - 512) * 512 + n];
        }
        for (int i = gt; i < 1088 * NN; i += gs) {
            int k = i >> 9, n = i & 511;
            float v;
            if (k < 512)       v = (k == n) ? 0.f : Whh[(512 + k) * 512 + n];
            else if (k < 1024) v = Whi[(k - 512) * 512 + n];
            else               v = Win[(k - 1024) * 512 + n];
            g_Wc1[i] = v;
        }
        for (int i = gt; i < 1088 * NN; i += gs) {
            int k = i >> 9, n = i & 511;
            float v;
            if (k < 512)       v = (k == n) ? 0.f : Whh[(1024 + k) * 512 + n];
            else if (k < 1024) v = Whi[(512 + (k - 512)) * 512 + n];
            else               v = Win[(k - 1024) * 512 + n];
            g_Wc2[i] = v;
        }
        for (int i = gt; i < 3 * NN; i += gs) {
            int l = i >> 9, n = i & 511;
            float v = b_hh[i] + b_in[n];
            if (l > 0) v += b_hi[(l - 1) * 512 + n];
            g_bc[i] = v;
        }
        for (int i = gt; i < 3 * NB; i += gs) {
            float v = h0[i];
            __stcg(&(&g_S[0][0][0])[i], v);
            __stcg(&(&g_S[1][0][0])[i], v);
        }
    }
    gridbar(gen);

    // ---- job decode (fixed per block) ----
    int l, tile, k0, nck;
    if (jid < 192) {
        l = 1 + jid / 96;
        int r = jid % 96;
        tile = r / 3;
        int s = r % 3;
        k0 = s * 352; nck = (s == 2) ? 12 : 11;
    } else {
        int r = jid - 192;
        l = 0; tile = r >> 1;
        k0 = (r & 1) * 288; nck = 9;
    }
    const int row0 = (tile >> 3) * 64, col0 = (tile & 7) * 64;
    const float* Wc = (l == 0) ? g_Wc0 : ((l == 1) ? g_Wc1 : g_Wc2);
    const int dbase = l ? 1024 : 512;
    const int tx = tid & 7, ty = tid >> 3;

    // combine-job decode (blocks 0..95)
    int cl = 0, ctile = 0, cj0 = 0, cnsp = 0;
    if (jid < 96) {
        if (jid < 64) { cl = 1 + (jid >> 5); ctile = jid & 31; cj0 = (cl - 1) * 96 + ctile * 3; cnsp = 3; }
        else          { cl = 0; ctile = jid - 64; cj0 = 192 + ctile * 2; cnsp = 2; }
    }
    const int crow0 = (ctile >> 3) * 64, ccol0 = (ctile & 7) * 64;

    // ---- wavefront ticks ----
    for (int kk = 0; kk < TT + 2; kk++) {
        const int cur = kk & 1, prev = cur ^ 1;
        const int t = kk - l;
        if (t >= 0 && t < TT) {
            unsigned long long acc[4][4];
#pragma unroll
            for (int m = 0; m < 4; m++)
#pragma unroll
                for (int j = 0; j < 4; j++) acc[m][j] = 0ull;

            auto load_chunk = [&](int ci, int buf) {
                int kabs = k0 + ci * 32;
                const float* src;
                int sA;
                if (kabs < 512)                { src = &g_S[prev][l][kabs];           sA = NN; }
                else if (l > 0 && kabs < 1024) { src = &g_S[prev][l - 1][kabs - 512]; sA = NN; }
                else { src = data + (size_t)t * (BB * II) + (kabs - dbase);           sA = II; }
                src += (size_t)row0 * sA;
#pragma unroll
                for (int i = 0; i < 4; i++) {
                    int u = tid * 4 + i;
                    int r = u >> 3, q = (u & 7) * 4;
                    cpa16(&As[buf][r * 36 + q], src + (size_t)r * sA + q);
                }
                const float* wsrc = Wc + (size_t)kabs * NN + col0;
#pragma unroll
                for (int i = 0; i < 4; i++) {
                    int u = tid * 4 + i;
                    int r = u >> 4, q = (u & 15) * 4;
                    cpa16(&Bs[buf][r * 64 + q], wsrc + (size_t)r * NN + q);
                }
                asm volatile("cp.async.commit_group;\n");
            };

            load_chunk(0, 0);
            for (int ci = 0; ci < nck; ci++) {
                int buf = ci & 1;
                if (ci + 1 < nck) {
                    load_chunk(ci + 1, buf ^ 1);
                    asm volatile("cp.async.wait_group 1;\n");
                } else {
                    asm volatile("cp.async.wait_group 0;\n");
                }
                __syncthreads();
                const float* A = As[buf];
                const float* Bp = Bs[buf];
#pragma unroll 8
                for (int k = 0; k < 32; k++) {
                    unsigned long long B0 = *(const unsigned long long*)&Bp[k * 64 + 0  + tx * 2];
                    unsigned long long B1 = *(const unsigned long long*)&Bp[k * 64 + 16 + tx * 2];
                    unsigned long long B2 = *(const unsigned long long*)&Bp[k * 64 + 32 + tx * 2];
                    unsigned long long B3 = *(const unsigned long long*)&Bp[k * 64 + 48 + tx * 2];
#pragma unroll
                    for (int m = 0; m < 4; m++) {
                        unsigned long long ap = bcast2(A[(ty + 16 * m) * 36 + k]);
                        fma2(acc[m][0], ap, B0);
                        fma2(acc[m][1], ap, B1);
                        fma2(acc[m][2], ap, B2);
                        fma2(acc[m][3], ap, B3);
                    }
                }
                __syncthreads();
            }
            float* P = &g_P[(size_t)jid * 4096];
#pragma unroll
            for (int m = 0; m < 4; m++)
#pragma unroll
                for (int j = 0; j < 4; j++) {
                    float2 v = upk(acc[m][j]);
                    *(float2*)&P[(ty + 16 * m) * 64 + j * 16 + tx * 2] = v;
                }
        }
        gridbar(gen);

        // combine: sum K-split partials + leaky-integrate + LeakyReLU
        if (jid < 96) {
            const int ct = kk - cl;
            if (ct >= 0 && ct < TT) {
                const float4* P0 = (const float4*)&g_P[(size_t)cj0 * 4096];
                const float* hold = g_S[prev][cl];
                float* dst = g_S[cur][cl];
                const float* bias = &g_bc[cl * NN];
                for (int i = tid; i < 1024; i += 128) {
                    float4 s = __ldcg(&P0[i]);
                    float4 s1 = __ldcg(&P0[1024 + i]);
                    s.x += s1.x; s.y += s1.y; s.z += s1.z; s.w += s1.w;
                    if (cnsp == 3) {
                        float4 s2 = __ldcg(&P0[2048 + i]);
                        s.x += s2.x; s.y += s2.y; s.z += s2.z; s.w += s2.w;
                    }
                    int e = i * 4;
                    int gr = crow0 + (e >> 6), gc = ccol0 + (e & 63);
                    float4 h = __ldcg((const float4*)&hold[gr * NN + gc]);
                    float4 b = *(const float4*)&bias[gc];
                    float4 o;
                    o.x = 0.5f * h.x + 0.5f * (s.x + b.x);
                    o.y = 0.5f * h.y + 0.5f * (s.y + b.y);
                    o.z = 0.5f * h.z + 0.5f * (s.z + b.z);
                    o.w = 0.5f * h.w + 0.5f * (s.w + b.w);
                    o.x = (o.x > 0.f) ? o.x : 0.01f * o.x;
                    o.y = (o.y > 0.f) ? o.y : 0.01f * o.y;
                    o.z = (o.z > 0.f) ? o.z : 0.01f * o.z;
                    o.w = (o.w > 0.f) ? o.w : 0.01f * o.w;
                    __stcg((float4*)&dst[gr * NN + gc], o);
                }
            }
        }
        gridbar(gen);
    }

    // ---- readout: 2560 dot products, one warp each, L2 reads ----
    {
        int warp0 = jid * 4 + (tid >> 5);
        int lane = tid & 31;
        for (int gw = warp0; gw < BB * 10; gw += NBLK * 4) {
            int b = gw / 10, c = gw % 10;
            const float* h = &g_S[1][2][b * NN];
            float s = 0.f;
            for (int k = lane; k < NN; k += 32)
                s += __ldcg(&h[k]) * Wfc[k * 10 + c];
#pragma unroll
            for (int o = 16; o; o >>= 1) s += __shfl_down_sync(0xffffffffu, s, o);
            if (lane == 0) out[b * 10 + c] = s + bfc[c];
        }
    }
}

extern "C" void kernel_launch(void* const* d_in, const int* in_sizes, int n_in,
                              void* d_out, int out_size) {
    const float* data = (const float*)d_in[0];
    const float* h0   = (const float*)d_in[1];
    const float* Win  = (const float*)d_in[2];
    const float* b_in = (const float*)d_in[3];
    const float* Whh  = (const float*)d_in[4];
    const float* b_hh = (const float*)d_in[5];
    const float* Whi  = (const float*)d_in[6];
    const float* b_hi = (const float*)d_in[7];
    const float* Wfc  = (const float*)d_in[8];
    const float* b_fc = (const float*)d_in[9];
    float* out = (float*)d_out;

    persist_kernel<<<NBLK, 128>>>(data, h0, Win, b_in, Whh, b_hh, Whi, b_hi,
                                  Wfc, b_fc, out);
}